// round 12
// baseline (speedup 1.0000x reference)
#include <cuda_runtime.h>

#define SEQ   2048
#define H     128
#define B     64
#define OUTF  512
#define NREC  64
#define NFC   84
#define THREADS 256

// Scratch: hidden-state history + per-batch progress watermark
__device__ float g_hs[(size_t)B * SEQ * H];
__device__ int   g_wm[B];

__device__ __forceinline__ unsigned long long ffma2(unsigned long long a,
                                                    unsigned long long b,
                                                    unsigned long long c) {
    unsigned long long d;
    asm("fma.rn.f32x2 %0, %1, %2, %3;" : "=l"(d) : "l"(a), "l"(b), "l"(c));
    return d;
}
__device__ __forceinline__ unsigned long long add2(unsigned long long a,
                                                   unsigned long long b) {
    unsigned long long d;
    asm("add.rn.f32x2 %0, %1, %2;" : "=l"(d) : "l"(a), "l"(b));
    return d;
}
__device__ __forceinline__ float hsum2(unsigned long long v) {
    float lo, hi;
    asm("mov.b64 {%0, %1}, %2;" : "=f"(lo), "=f"(hi) : "l"(v));
    return lo + hi;
}
__device__ __forceinline__ float ex2f(float x) {
    float y; asm("ex2.approx.f32 %0, %1;" : "=f"(y) : "f"(x)); return y;
}
__device__ __forceinline__ float rcpf(float x) {
    float y; asm("rcp.approx.f32 %0, %1;" : "=f"(y) : "f"(x)); return y;
}
__device__ __forceinline__ float fast_sigmoid(float x) {
    return rcpf(1.0f + ex2f(-1.4426950408889634f * x));
}
__device__ __forceinline__ float tanh_fast(float x) {
    float y; asm("tanh.approx.f32 %0, %1;" : "=f"(y) : "f"(x)); return y;
}
// smem acquire/release ops on the warp step counters
__device__ __forceinline__ int ld_acq_shared(unsigned int addr) {
    int v;
    asm volatile("ld.acquire.cta.shared.b32 %0, [%1];"
                 : "=r"(v) : "r"(addr) : "memory");
    return v;
}
__device__ __forceinline__ void st_rel_shared(unsigned int addr, int v) {
    asm volatile("st.release.cta.shared.b32 [%0], %1;"
                 :: "r"(addr), "r"(v) : "memory");
}

__global__ void init_wm_kernel() {
    if (threadIdx.x < B) g_wm[threadIdx.x] = 0;
}

// Recurrence smem: parity p region at pool + p*264 floats:
//   copy A (read by half 0) at +0, copy B (read by half 1) at +132.
// Counters (8 ints, one per warp) live after the two regions.
#define PAR_STRIDE 264

__global__ void __launch_bounds__(THREADS, 1) fused_kernel(
    const float* __restrict__ latent,  // (64,128)
    const float* __restrict__ W_hh,    // (384,128)
    const float* __restrict__ b_ih,    // (384,)
    const float* __restrict__ b_hh,    // (384,)
    const float* __restrict__ fc_W,    // (512,128)
    const float* __restrict__ fc_b,    // (512,)
    float* __restrict__ out)           // (64,2048,512)
{
    __shared__ __align__(16) float pool[32 * H];

    const int tid = threadIdx.x;

    if (blockIdx.x < NREC) {
        // === Recurrence: barrier-free skewed ring over 8 warps.              ===
        // === Warp w owns 16 h-elements (8 per dot-half). The k-loop is       ===
        // === rotated so each warp consumes its own chunk first; foreign      ===
        // === chunks are gated by per-warp step counters (acquire/release).   ===
        const int b    = blockIdx.x;
        const int lane = tid & 31;
        const int w    = tid >> 5;            // 0..7
        const int half = lane & 1;            // low/high 64 elems of each dot
        const int p    = lane >> 1;           // pair index 0..15
        // warp w owns li in [8w,8w+8) (lower half) and [64+8w,64+8w+8) (upper)
        const int li   = (p < 8) ? (w * 8 + p) : (64 + w * 8 + (p - 8));

        int* cnt = (int*)(pool + 2 * PAR_STRIDE);   // 8 per-warp step counters
        unsigned int cnt_a = (unsigned int)__cvta_generic_to_shared(cnt);

        // Three half-rows of W_hh in registers, loaded in ROTATED chunk order:
        // slot 4*d+u  <->  h-floats of chunk cd=(w+d)&7, u64 u within chunk.
        unsigned long long wr[32], wz[32], wn[32];
        {
            const unsigned long long* W64 = (const unsigned long long*)W_hh;
            const size_t o  = (size_t)half * 32;
            const size_t rr = (size_t)li * 64 + o;
            const size_t rz = (size_t)(H + li) * 64 + o;
            const size_t rn = (size_t)(2 * H + li) * 64 + o;
            #pragma unroll
            for (int d = 0; d < 8; d++) {
                const int cd = (w + d) & 7;
                #pragma unroll
                for (int u = 0; u < 4; u++) {
                    wr[4 * d + u] = W64[rr + 4 * cd + u];
                    wz[4 * d + u] = W64[rz + 4 * cd + u];
                    wn[4 * d + u] = W64[rn + 4 * cd + u];
                }
            }
        }

        const float bs_r   = b_ih[li] + b_hh[li];
        const float bs_z   = b_ih[H + li] + b_hh[H + li];
        const float bs_n   = b_hh[2 * H + li];
        const float b_in_i = b_ih[2 * H + li];

        float hold = latent[(size_t)b * H + li];
        pool[half * 132 + li] = hold;          // init parity-0 copies
        if (tid < 8) cnt[tid] = 0;
        __syncthreads();                       // once, before the loop

        const int widx = half * 132 + li;      // write index within a region
        const int roff = half ? 196 : 0;       // read offset within a region

        const ulonglong2* rb0 = (const ulonglong2*)(pool + roff);
        const ulonglong2* rb1 = (const ulonglong2*)(pool + PAR_STRIDE + roff);
        float* wb0 = pool;
        float* wb1 = pool + PAR_STRIDE;

        float* hs_base = g_hs + (size_t)b * SEQ * H + li;

        auto step = [&](const ulonglong2* h2, float* wbase, int t) {
            // Up-front acquire reads of the 7 foreign counters (steady-state hit)
            int cv[8];
            #pragma unroll
            for (int d = 1; d < 8; d++)
                cv[d] = ld_acq_shared(cnt_a + (((w + d) & 7) << 2));

            unsigned long long ar = 0ull, az = 0ull, an = 0ull;
            #pragma unroll
            for (int d = 0; d < 8; d++) {
                if (d > 0 && cv[d] < t) {       // slow path: producer not done yet
                    const unsigned int a = cnt_a + (((w + d) & 7) << 2);
                    int v;
                    do { v = ld_acq_shared(a); } while (v < t);
                }
                const int cd = (w + d) & 7;
                #pragma unroll
                for (int j = 0; j < 2; j++) {
                    ulonglong2 hv = h2[2 * cd + j];
                    const int s = 4 * d + 2 * j;
                    ar = ffma2(wr[s],     hv.x, ar);
                    az = ffma2(wz[s],     hv.x, az);
                    an = ffma2(wn[s],     hv.x, an);
                    ar = ffma2(wr[s + 1], hv.y, ar);
                    az = ffma2(wz[s + 1], hv.y, az);
                    an = ffma2(wn[s + 1], hv.y, an);
                }
            }
            float sr = hsum2(ar);
            float sn = hsum2(an);
            float sz = hsum2(az);
            sr += __shfl_xor_sync(0xffffffffu, sr, 1);
            sn += __shfl_xor_sync(0xffffffffu, sn, 1);
            sz += __shfl_xor_sync(0xffffffffu, sz, 1);

            float r  = fast_sigmoid(sr + bs_r);
            float z  = fast_sigmoid(sz + bs_z);
            float n  = tanh_fast(fmaf(r, sn + bs_n, b_in_i));
            float hn = fmaf(z, hold - n, n);     // (1-z)*n + z*h
            hold = hn;

            wbase[widx] = hn;                    // publish own h element
            if (half == 0) hs_base[(size_t)t * H] = hn;
            __syncwarp();                        // own-warp STS visible warp-wide
            if (lane == 0) st_rel_shared(cnt_a + (w << 2), t + 1);
        };

        for (int to = 0; to < SEQ; to += 32) {
            #pragma unroll 1
            for (int ti = 0; ti < 32; ti += 2) {
                step(rb0, wb1, to + ti);         // parity 0 -> 1
                step(rb1, wb0, to + ti + 1);     // parity 1 -> 0
            }
            if (tid == 0) {                      // all warps' stores for this block
                #pragma unroll 1
                for (int v = 1; v < 8; v++)
                    while (ld_acq_shared(cnt_a + (v << 2)) < to + 32) { }
                __threadfence();
                atomicExch(&g_wm[b], to + 32);
            }
        }
    } else {
        // ================= FC role: consume hs tiles as produced =================
        const int fcid = blockIdx.x - NREC;   // 0..83
        const int cb   = fcid / 21;           // fixed 128-col block
        const int sub  = fcid % 21;
        const int col  = cb * H + (tid & 127);
        const int grp  = tid >> 7;            // 2 row-groups over the 32-row tile

        unsigned long long w[64];
        {
            const unsigned long long* Wr =
                (const unsigned long long*)(fc_W + (size_t)col * H);
            #pragma unroll
            for (int k = 0; k < 64; k++) w[k] = Wr[k];
        }
        const float bias = fc_b[col];

        for (int ent = sub; ent < 64 * B; ent += 21) {
            const int tblk = ent >> 6;
            const int bb   = ent & 63;

            if (tid == 0) {
                const int need = (tblk + 1) * 32;
                while (atomicAdd(&g_wm[bb], 0) < need) __nanosleep(256);
            }
            __syncthreads();

            // Stage 32x128 fp32 hs tile (16 KB)
            const float4* src =
                (const float4*)(g_hs + ((size_t)bb * SEQ + (size_t)tblk * 32) * H);
            float4* dst = (float4*)pool;
            #pragma unroll
            for (int it = 0; it < 4; it++) {
                int idx = tid + it * THREADS;
                dst[idx] = src[idx];
            }
            __syncthreads();

            for (int r = grp; r < 32; r += 2) {
                const ulonglong2* hrow = (const ulonglong2*)(pool + r * H);
                unsigned long long a0 = 0ull, a1 = 0ull;
                #pragma unroll
                for (int k = 0; k < 32; k++) {
                    ulonglong2 hv = hrow[k];
                    a0 = ffma2(w[2 * k    ], hv.x, a0);
                    a1 = ffma2(w[2 * k + 1], hv.y, a1);
                }
                out[((size_t)bb * SEQ + (size_t)tblk * 32 + r) * OUTF + col] =
                    hsum2(add2(a0, a1)) + bias;
            }
            __syncthreads();
        }
    }
}

extern "C" void kernel_launch(void* const* d_in, const int* in_sizes, int n_in,
                              void* d_out, int out_size) {
    const float* latent = (const float*)d_in[0];
    const float* W_hh   = (const float*)d_in[1];
    const float* b_ih   = (const float*)d_in[2];
    const float* b_hh   = (const float*)d_in[3];
    const float* fc_W   = (const float*)d_in[4];
    const float* fc_b   = (const float*)d_in[5];
    float* out = (float*)d_out;

    init_wm_kernel<<<1, 64>>>();
    fused_kernel<<<NREC + NFC, THREADS>>>(latent, W_hh, b_ih, b_hh, fc_W, fc_b, out);
}

// round 13
// speedup vs baseline: 2.7882x; 2.7882x over previous
#include <cuda_runtime.h>

#define SEQ   2048
#define H     128
#define B     64
#define OUTF  512
#define NREC  64
#define NFC   84
#define THREADS 256

// Scratch: hidden-state history + per-batch progress watermark
__device__ float g_hs[(size_t)B * SEQ * H];
__device__ int   g_wm[B];

__device__ __forceinline__ unsigned long long ffma2(unsigned long long a,
                                                    unsigned long long b,
                                                    unsigned long long c) {
    unsigned long long d;
    asm("fma.rn.f32x2 %0, %1, %2, %3;" : "=l"(d) : "l"(a), "l"(b), "l"(c));
    return d;
}
__device__ __forceinline__ unsigned long long add2(unsigned long long a,
                                                   unsigned long long b) {
    unsigned long long d;
    asm("add.rn.f32x2 %0, %1, %2;" : "=l"(d) : "l"(a), "l"(b));
    return d;
}
__device__ __forceinline__ unsigned long long mul2(unsigned long long a,
                                                   unsigned long long b) {
    unsigned long long d;
    asm("mul.rn.f32x2 %0, %1, %2;" : "=l"(d) : "l"(a), "l"(b));
    return d;
}
__device__ __forceinline__ unsigned long long pack2(float lo, float hi) {
    unsigned long long v;
    asm("mov.b64 %0, {%1, %2};" : "=l"(v) : "f"(lo), "f"(hi));
    return v;
}
__device__ __forceinline__ float hsum2(unsigned long long v) {
    float lo, hi;
    asm("mov.b64 {%0, %1}, %2;" : "=f"(lo), "=f"(hi) : "l"(v));
    return lo + hi;
}
__device__ __forceinline__ float ex2f(float x) {
    float y; asm("ex2.approx.f32 %0, %1;" : "=f"(y) : "f"(x)); return y;
}
__device__ __forceinline__ float rcpf(float x) {
    float y; asm("rcp.approx.f32 %0, %1;" : "=f"(y) : "f"(x)); return y;
}
// sigmoid with PRE-SCALED argument: expects s = -log2(e) * x
__device__ __forceinline__ float sigmoid_scaled(float s) {
    return rcpf(1.0f + ex2f(s));
}
__device__ __forceinline__ float tanh_fast(float x) {
    float y; asm("tanh.approx.f32 %0, %1;" : "=f"(y) : "f"(x)); return y;
}

#define NEG_LOG2E -1.4426950408889634f

__global__ void init_wm_kernel() {
    if (threadIdx.x < B) g_wm[threadIdx.x] = 0;
}

// Recurrence smem layout: parity p at pool + p*264:
//   copy A (read by half 0) at +0,  copy B (read by half 1) at +132
// 132-float shift => the two broadcast lines land in different banks.
#define PAR_STRIDE 264

__global__ void __launch_bounds__(THREADS, 1) fused_kernel(
    const float* __restrict__ latent,  // (64,128)
    const float* __restrict__ W_hh,    // (384,128)
    const float* __restrict__ b_ih,    // (384,)
    const float* __restrict__ b_hh,    // (384,)
    const float* __restrict__ fc_W,    // (512,128)
    const float* __restrict__ fc_b,    // (512,)
    float* __restrict__ out)           // (64,2048,512)
{
    __shared__ __align__(16) float pool[32 * H];

    const int tid = threadIdx.x;

    if (blockIdx.x < NREC) {
        // === Recurrence: one batch/CTA; a lane PAIR owns hidden index li and ===
        // === computes r, z, n dots itself. Ping-pong h, ONE barrier per step. ===
        const int b    = blockIdx.x;
        const int lane = tid & 31;
        const int warp = tid >> 5;            // 0..7
        const int half = lane & 1;            // low/high 64 elems of each dot
        const int li   = warp * 16 + (lane >> 1);   // 0..127

        // Three half-rows of W_hh in registers: 96 u64 = 192 regs.
        // r/z rows are PRE-SCALED by -log2(e): their dots come out ready for
        // sigmoid_scaled (saves the inner multiply on the critical chain).
        unsigned long long wr[32], wz[32], wn[32];
        {
            const unsigned long long* W64 = (const unsigned long long*)W_hh;
            const size_t o  = (size_t)half * 32;
            const size_t rr = (size_t)li * 64;
            const size_t rz = (size_t)(H + li) * 64;
            const size_t rn = (size_t)(2 * H + li) * 64;
            const unsigned long long scl = pack2(NEG_LOG2E, NEG_LOG2E);
            #pragma unroll
            for (int k = 0; k < 32; k++) wr[k] = mul2(W64[rr + o + k], scl);
            #pragma unroll
            for (int k = 0; k < 32; k++) wz[k] = mul2(W64[rz + o + k], scl);
            #pragma unroll
            for (int k = 0; k < 32; k++) wn[k] = W64[rn + o + k];
        }

        // Biases: r/z pre-scaled to match the scaled weights
        const float bs_r   = NEG_LOG2E * (b_ih[li] + b_hh[li]);
        const float bs_z   = NEG_LOG2E * (b_ih[H + li] + b_hh[H + li]);
        const float bs_n   = b_hh[2 * H + li];
        const float b_in_i = b_ih[2 * H + li];

        // h[li] lives in a register across steps (owned by this lane pair)
        float hold = latent[(size_t)b * H + li];
        pool[half * 132 + li] = hold;          // init parity-0 buffers
        __syncthreads();

        const int widx = half * 132 + li;      // write index within a parity region
        const int roff = half ? 196 : 0;       // read offset within a parity region

        const float* rb0 = pool + roff;              // parity 0 read base
        const float* rb1 = pool + PAR_STRIDE + roff; // parity 1 read base
        float*       wb0 = pool;                     // parity 0 write base
        float*       wb1 = pool + PAR_STRIDE;

        float* hs_base = g_hs + (size_t)b * SEQ * H + li;

        // one GRU step: read h from rbase, write new h to wbase
        auto step = [&](const float* rbase, float* wbase, int t) {
            const ulonglong2* h2 = (const ulonglong2*)rbase;
            unsigned long long ar = 0ull, az = 0ull, an = 0ull;
            #pragma unroll
            for (int k = 0; k < 16; k++) {
                ulonglong2 hv = h2[k];
                ar = ffma2(wr[2 * k], hv.x, ar);
                az = ffma2(wz[2 * k], hv.x, az);
                an = ffma2(wn[2 * k], hv.x, an);
                ar = ffma2(wr[2 * k + 1], hv.y, ar);
                az = ffma2(wz[2 * k + 1], hv.y, az);
                an = ffma2(wn[2 * k + 1], hv.y, an);
            }
            // Critical path: sr -> r -> n -> hn. Reduce sr first.
            float sr = hsum2(ar);
            float sn = hsum2(an);
            float sz = hsum2(az);
            sr += __shfl_xor_sync(0xffffffffu, sr, 1);
            sn += __shfl_xor_sync(0xffffffffu, sn, 1);
            sz += __shfl_xor_sync(0xffffffffu, sz, 1);

            float r   = sigmoid_scaled(sr + bs_r);    // pre-scaled dot
            float snb = sn + bs_n;                    // off critical path
            float z   = sigmoid_scaled(sz + bs_z);    // parallel chain
            float n   = tanh_fast(fmaf(r, snb, b_in_i));  // single MUFU
            float hn  = fmaf(z, hold - n, n);         // (1-z)*n + z*h
            hold = hn;

            wbase[widx] = hn;                    // ping-pong write (no WAR race)
            if (half == 0) hs_base[(size_t)t * H] = hn;
            __syncthreads();                     // single barrier per step
        };

        for (int to = 0; to < SEQ; to += 32) {
            #pragma unroll 1
            for (int ti = 0; ti < 32; ti += 2) {
                step(rb0, wb1, to + ti);         // even step: parity 0 -> 1
                step(rb1, wb0, to + ti + 1);     // odd  step: parity 1 -> 0
            }
            if (tid == 0) {
                __threadfence();
                atomicExch(&g_wm[b], to + 32);
            }
        }
    } else {
        // ================= FC role: consume hs tiles as produced =================
        const int fcid = blockIdx.x - NREC;   // 0..83
        const int cb   = fcid / 21;           // fixed 128-col block
        const int sub  = fcid % 21;
        const int col  = cb * H + (tid & 127);
        const int grp  = tid >> 7;            // 2 row-groups over the 32-row tile

        unsigned long long w[64];
        {
            const unsigned long long* Wr =
                (const unsigned long long*)(fc_W + (size_t)col * H);
            #pragma unroll
            for (int k = 0; k < 64; k++) w[k] = Wr[k];
        }
        const float bias = fc_b[col];

        for (int ent = sub; ent < 64 * B; ent += 21) {
            const int tblk = ent >> 6;
            const int bb   = ent & 63;

            if (tid == 0) {
                const int need = (tblk + 1) * 32;
                while (atomicAdd(&g_wm[bb], 0) < need) __nanosleep(256);
            }
            __syncthreads();

            // Stage 32x128 fp32 hs tile (16 KB)
            const float4* src =
                (const float4*)(g_hs + ((size_t)bb * SEQ + (size_t)tblk * 32) * H);
            float4* dst = (float4*)pool;
            #pragma unroll
            for (int it = 0; it < 4; it++) {
                int idx = tid + it * THREADS;
                dst[idx] = src[idx];
            }
            __syncthreads();

            for (int r = grp; r < 32; r += 2) {
                const ulonglong2* hrow = (const ulonglong2*)(pool + r * H);
                unsigned long long a0 = 0ull, a1 = 0ull;
                #pragma unroll
                for (int k = 0; k < 32; k++) {
                    ulonglong2 hv = hrow[k];
                    a0 = ffma2(w[2 * k    ], hv.x, a0);
                    a1 = ffma2(w[2 * k + 1], hv.y, a1);
                }
                out[((size_t)bb * SEQ + (size_t)tblk * 32 + r) * OUTF + col] =
                    hsum2(add2(a0, a1)) + bias;
            }
            __syncthreads();
        }
    }
}

extern "C" void kernel_launch(void* const* d_in, const int* in_sizes, int n_in,
                              void* d_out, int out_size) {
    const float* latent = (const float*)d_in[0];
    const float* W_hh   = (const float*)d_in[1];
    const float* b_ih   = (const float*)d_in[2];
    const float* b_hh   = (const float*)d_in[3];
    const float* fc_W   = (const float*)d_in[4];
    const float* fc_b   = (const float*)d_in[5];
    float* out = (float*)d_out;

    init_wm_kernel<<<1, 64>>>();
    fused_kernel<<<NREC + NFC, THREADS>>>(latent, W_hh, b_ih, b_hh, fc_W, fc_b, out);
}

// round 14
// speedup vs baseline: 2.7993x; 1.0040x over previous
#include <cuda_runtime.h>

#define SEQ   2048
#define H     128
#define B     64
#define OUTF  512
#define NREC  64
#define NFC   84
#define THREADS 256

// Scratch: hidden-state history + per-batch progress watermark
__device__ float g_hs[(size_t)B * SEQ * H];
__device__ int   g_wm[B];

__device__ __forceinline__ unsigned long long ffma2(unsigned long long a,
                                                    unsigned long long b,
                                                    unsigned long long c) {
    unsigned long long d;
    asm("fma.rn.f32x2 %0, %1, %2, %3;" : "=l"(d) : "l"(a), "l"(b), "l"(c));
    return d;
}
__device__ __forceinline__ unsigned long long add2(unsigned long long a,
                                                   unsigned long long b) {
    unsigned long long d;
    asm("add.rn.f32x2 %0, %1, %2;" : "=l"(d) : "l"(a), "l"(b));
    return d;
}
__device__ __forceinline__ float hsum2(unsigned long long v) {
    float lo, hi;
    asm("mov.b64 {%0, %1}, %2;" : "=f"(lo), "=f"(hi) : "l"(v));
    return lo + hi;
}
__device__ __forceinline__ float ex2f(float x) {
    float y; asm("ex2.approx.f32 %0, %1;" : "=f"(y) : "f"(x)); return y;
}
__device__ __forceinline__ float rcpf(float x) {
    float y; asm("rcp.approx.f32 %0, %1;" : "=f"(y) : "f"(x)); return y;
}
__device__ __forceinline__ float fast_sigmoid(float x) {
    return rcpf(1.0f + ex2f(-1.4426950408889634f * x));
}
__device__ __forceinline__ float tanh_fast(float x) {
    float y; asm("tanh.approx.f32 %0, %1;" : "=f"(y) : "f"(x)); return y;
}

__global__ void init_wm_kernel() {
    if (threadIdx.x < B) g_wm[threadIdx.x] = 0;
}

// Recurrence smem layout: parity p at pool + p*264:
//   copy A (read by half 0) at +0,  copy B (read by half 1) at +132
// 132-float shift => the two broadcast lines land in different banks.
#define PAR_STRIDE 264

__global__ void __launch_bounds__(THREADS, 1) fused_kernel(
    const float* __restrict__ latent,  // (64,128)
    const float* __restrict__ W_hh,    // (384,128)
    const float* __restrict__ b_ih,    // (384,)
    const float* __restrict__ b_hh,    // (384,)
    const float* __restrict__ fc_W,    // (512,128)
    const float* __restrict__ fc_b,    // (512,)
    float* __restrict__ out)           // (64,2048,512)
{
    __shared__ __align__(16) float pool[32 * H];

    const int tid = threadIdx.x;

    if (blockIdx.x < NREC) {
        // === Recurrence: one batch/CTA; a lane PAIR owns hidden index li and ===
        // === computes r, z, n dots itself. Gate completion is STAGGERED so   ===
        // === r's reduce/sigmoid chain hides under the n/z FMA stream.        ===
        const int b    = blockIdx.x;
        const int lane = tid & 31;
        const int warp = tid >> 5;            // 0..7
        const int half = lane & 1;            // low/high 64 elems of each dot
        const int li   = warp * 16 + (lane >> 1);   // 0..127

        // Three half-rows of W_hh in registers: 96 u64 = 192 regs
        unsigned long long wr[32], wz[32], wn[32];
        {
            const unsigned long long* W64 = (const unsigned long long*)W_hh;
            const size_t o  = (size_t)half * 32;
            const size_t rr = (size_t)li * 64;
            const size_t rz = (size_t)(H + li) * 64;
            const size_t rn = (size_t)(2 * H + li) * 64;
            #pragma unroll
            for (int k = 0; k < 32; k++) wr[k] = W64[rr + o + k];
            #pragma unroll
            for (int k = 0; k < 32; k++) wz[k] = W64[rz + o + k];
            #pragma unroll
            for (int k = 0; k < 32; k++) wn[k] = W64[rn + o + k];
        }

        const float bs_r   = b_ih[li] + b_hh[li];
        const float bs_z   = b_ih[H + li] + b_hh[H + li];
        const float bs_n   = b_hh[2 * H + li];
        const float b_in_i = b_ih[2 * H + li];

        // h[li] lives in a register across steps (owned by this lane pair)
        float hold = latent[(size_t)b * H + li];
        pool[half * 132 + li] = hold;          // init parity-0 buffers
        __syncthreads();

        const int widx = half * 132 + li;      // write index within a parity region
        const int roff = half ? 196 : 0;       // read offset within a parity region

        const float* rb0 = pool + roff;              // parity 0 read base
        const float* rb1 = pool + PAR_STRIDE + roff; // parity 1 read base
        float*       wb0 = pool;                     // parity 0 write base
        float*       wb1 = pool + PAR_STRIDE;

        float* hs_base = g_hs + (size_t)b * SEQ * H + li;

        // one GRU step: read h from rbase, write new h to wbase.
        // Gate finishing order: r first (longest chain), then n, then z.
        auto step = [&](const float* rbase, float* wbase, int t) {
            const ulonglong2* h2 = (const ulonglong2*)rbase;
            unsigned long long ar = 0ull, az = 0ull, an = 0ull;
            #pragma unroll
            for (int k = 0; k < 12; k++) {
                ulonglong2 hv = h2[k];
                ar = ffma2(wr[2 * k], hv.x, ar);
                az = ffma2(wz[2 * k], hv.x, az);
                an = ffma2(wn[2 * k], hv.x, an);
                ar = ffma2(wr[2 * k + 1], hv.y, ar);
                az = ffma2(wz[2 * k + 1], hv.y, az);
                an = ffma2(wn[2 * k + 1], hv.y, an);
            }
            // Shared tail operands for k = 12..15
            ulonglong2 hv12 = h2[12], hv13 = h2[13], hv14 = h2[14], hv15 = h2[15];

            // --- finish r (two short chains), launch its reduction early ---
            {
                unsigned long long a = ffma2(wr[24], hv12.x, ar);
                unsigned long long bch = ffma2(wr[25], hv12.y, 0ull);
                a   = ffma2(wr[26], hv13.x, a);
                bch = ffma2(wr[27], hv13.y, bch);
                a   = ffma2(wr[28], hv14.x, a);
                bch = ffma2(wr[29], hv14.y, bch);
                a   = ffma2(wr[30], hv15.x, a);
                bch = ffma2(wr[31], hv15.y, bch);
                ar  = add2(a, bch);
            }
            float sr  = hsum2(ar);
            float sro = __shfl_xor_sync(0xffffffffu, sr, 1);

            // --- finish n ---
            {
                unsigned long long a = ffma2(wn[24], hv12.x, an);
                unsigned long long bch = ffma2(wn[25], hv12.y, 0ull);
                a   = ffma2(wn[26], hv13.x, a);
                bch = ffma2(wn[27], hv13.y, bch);
                a   = ffma2(wn[28], hv14.x, a);
                bch = ffma2(wn[29], hv14.y, bch);
                a   = ffma2(wn[30], hv15.x, a);
                bch = ffma2(wn[31], hv15.y, bch);
                an  = add2(a, bch);
            }
            float sn  = hsum2(an);
            float sno = __shfl_xor_sync(0xffffffffu, sn, 1);
            float r   = fast_sigmoid(sr + sro + bs_r);   // overlaps z's FMAs

            // --- finish z (needed only at the final hn fma) ---
            {
                unsigned long long a = ffma2(wz[24], hv12.x, az);
                unsigned long long bch = ffma2(wz[25], hv12.y, 0ull);
                a   = ffma2(wz[26], hv13.x, a);
                bch = ffma2(wz[27], hv13.y, bch);
                a   = ffma2(wz[28], hv14.x, a);
                bch = ffma2(wz[29], hv14.y, bch);
                a   = ffma2(wz[30], hv15.x, a);
                bch = ffma2(wz[31], hv15.y, bch);
                az  = add2(a, bch);
            }
            float sz  = hsum2(az);
            float szo = __shfl_xor_sync(0xffffffffu, sz, 1);

            float n  = tanh_fast(fmaf(r, sn + sno + bs_n, b_in_i));
            float z  = fast_sigmoid(sz + szo + bs_z);
            float hn = fmaf(z, hold - n, n);     // (1-z)*n + z*h
            hold = hn;

            wbase[widx] = hn;                    // ping-pong write (no WAR race)
            __syncthreads();                     // single barrier per step
            if (half == 0) hs_base[(size_t)t * H] = hn;  // overlaps next dot
        };

        for (int to = 0; to < SEQ; to += 32) {
            #pragma unroll 1
            for (int ti = 0; ti < 32; ti += 2) {
                step(rb0, wb1, to + ti);         // even step: parity 0 -> 1
                step(rb1, wb0, to + ti + 1);     // odd  step: parity 1 -> 0
            }
            // ensure all post-barrier STGs for steps <= to+31 are ordered
            // before the watermark publish (amortized: once per 32 steps)
            __syncthreads();
            if (tid == 0) {
                __threadfence();
                atomicExch(&g_wm[b], to + 32);
            }
        }
    } else {
        // ================= FC role: consume hs tiles as produced =================
        const int fcid = blockIdx.x - NREC;   // 0..83
        const int cb   = fcid / 21;           // fixed 128-col block
        const int sub  = fcid % 21;
        const int col  = cb * H + (tid & 127);
        const int grp  = tid >> 7;            // 2 row-groups over the 32-row tile

        unsigned long long w[64];
        {
            const unsigned long long* Wr =
                (const unsigned long long*)(fc_W + (size_t)col * H);
            #pragma unroll
            for (int k = 0; k < 64; k++) w[k] = Wr[k];
        }
        const float bias = fc_b[col];

        for (int ent = sub; ent < 64 * B; ent += 21) {
            const int tblk = ent >> 6;
            const int bb   = ent & 63;

            if (tid == 0) {
                const int need = (tblk + 1) * 32;
                while (atomicAdd(&g_wm[bb], 0) < need) __nanosleep(256);
            }
            __syncthreads();

            // Stage 32x128 fp32 hs tile (16 KB)
            const float4* src =
                (const float4*)(g_hs + ((size_t)bb * SEQ + (size_t)tblk * 32) * H);
            float4* dst = (float4*)pool;
            #pragma unroll
            for (int it = 0; it < 4; it++) {
                int idx = tid + it * THREADS;
                dst[idx] = src[idx];
            }
            __syncthreads();

            for (int r = grp; r < 32; r += 2) {
                const ulonglong2* hrow = (const ulonglong2*)(pool + r * H);
                unsigned long long a0 = 0ull, a1 = 0ull;
                #pragma unroll
                for (int k = 0; k < 32; k++) {
                    ulonglong2 hv = hrow[k];
                    a0 = ffma2(w[2 * k    ], hv.x, a0);
                    a1 = ffma2(w[2 * k + 1], hv.y, a1);
                }
                out[((size_t)bb * SEQ + (size_t)tblk * 32 + r) * OUTF + col] =
                    hsum2(add2(a0, a1)) + bias;
            }
            __syncthreads();
        }
    }
}

extern "C" void kernel_launch(void* const* d_in, const int* in_sizes, int n_in,
                              void* d_out, int out_size) {
    const float* latent = (const float*)d_in[0];
    const float* W_hh   = (const float*)d_in[1];
    const float* b_ih   = (const float*)d_in[2];
    const float* b_hh   = (const float*)d_in[3];
    const float* fc_W   = (const float*)d_in[4];
    const float* fc_b   = (const float*)d_in[5];
    float* out = (float*)d_out;

    init_wm_kernel<<<1, 64>>>();
    fused_kernel<<<NREC + NFC, THREADS>>>(latent, W_hh, b_ih, b_hh, fc_W, fc_b, out);
}

// round 15
// speedup vs baseline: 2.8077x; 1.0030x over previous
#include <cuda_runtime.h>

#define SEQ   2048
#define H     128
#define B     64
#define OUTF  512
#define NREC  64
#define NFC   84
#define THREADS 256

// Scratch: hidden-state history + per-batch progress watermark
__device__ float g_hs[(size_t)B * SEQ * H];
__device__ int   g_wm[B];

__device__ __forceinline__ unsigned long long ffma2(unsigned long long a,
                                                    unsigned long long b,
                                                    unsigned long long c) {
    unsigned long long d;
    asm("fma.rn.f32x2 %0, %1, %2, %3;" : "=l"(d) : "l"(a), "l"(b), "l"(c));
    return d;
}
__device__ __forceinline__ unsigned long long add2(unsigned long long a,
                                                   unsigned long long b) {
    unsigned long long d;
    asm("add.rn.f32x2 %0, %1, %2;" : "=l"(d) : "l"(a), "l"(b));
    return d;
}
__device__ __forceinline__ unsigned long long mul2(unsigned long long a,
                                                   unsigned long long b) {
    unsigned long long d;
    asm("mul.rn.f32x2 %0, %1, %2;" : "=l"(d) : "l"(a), "l"(b));
    return d;
}
__device__ __forceinline__ unsigned long long pack2(float lo, float hi) {
    unsigned long long v;
    asm("mov.b64 %0, {%1, %2};" : "=l"(v) : "f"(lo), "f"(hi));
    return v;
}
__device__ __forceinline__ float hsum2(unsigned long long v) {
    float lo, hi;
    asm("mov.b64 {%0, %1}, %2;" : "=f"(lo), "=f"(hi) : "l"(v));
    return lo + hi;
}
__device__ __forceinline__ float ex2f(float x) {
    float y; asm("ex2.approx.f32 %0, %1;" : "=f"(y) : "f"(x)); return y;
}
__device__ __forceinline__ float rcpf(float x) {
    float y; asm("rcp.approx.f32 %0, %1;" : "=f"(y) : "f"(x)); return y;
}
__device__ __forceinline__ float tanh_fast(float x) {
    float y; asm("tanh.approx.f32 %0, %1;" : "=f"(y) : "f"(x)); return y;
}

#define NEG_LOG2E -1.4426950408889634f

__global__ void init_wm_kernel() {
    if (threadIdx.x < B) g_wm[threadIdx.x] = 0;
}

// Recurrence smem layout: parity p at pool + p*264:
//   copy A at +0 (full-dot broadcast reads + even-lane n-half reads),
//   copy B at +132 (odd-lane n-half reads, bank-shifted).
#define PAR_STRIDE 264

__global__ void __launch_bounds__(THREADS, 1) fused_kernel(
    const float* __restrict__ latent,  // (64,128)
    const float* __restrict__ W_hh,    // (384,128)
    const float* __restrict__ b_ih,    // (384,)
    const float* __restrict__ b_hh,    // (384,)
    const float* __restrict__ fc_W,    // (512,128)
    const float* __restrict__ fc_b,    // (512,)
    float* __restrict__ out)           // (64,2048,512)
{
    __shared__ __align__(16) float pool[32 * H];

    const int tid = threadIdx.x;

    if (blockIdx.x < NREC) {
        // === Recurrence: lane EVEN owns the full r-dot, lane ODD the full   ===
        // === z-dot (no shfl for either); only the n-dot is pair-split.      ===
        // === r/z sigmoid chains hide under the n-dot's FMA stream.          ===
        const int b    = blockIdx.x;
        const int lane = tid & 31;
        const int warp = tid >> 5;            // 0..7
        const int half = lane & 1;            // 0: r-gate owner, 1: z-gate owner
        const int li   = warp * 16 + (lane >> 1);   // 0..127

        // wA: FULL row of the owned sigmoid gate (r or z), PRE-SCALED by
        // -log2(e) so the dot is ex2-ready. wN: half row of the n gate.
        unsigned long long wA[64], wN[32];
        {
            const unsigned long long* W64 = (const unsigned long long*)W_hh;
            const size_t rowA = (size_t)(half ? (H + li) : li) * 64;
            const size_t rowN = (size_t)(2 * H + li) * 64 + (size_t)half * 32;
            const unsigned long long scl = pack2(NEG_LOG2E, NEG_LOG2E);
            #pragma unroll
            for (int k = 0; k < 64; k++) wA[k] = mul2(W64[rowA + k], scl);
            #pragma unroll
            for (int k = 0; k < 32; k++) wN[k] = W64[rowN + k];
        }

        // Bias seeds: gate-A bias pre-scaled and folded into the accumulator;
        // n-gate's b_hh folded into the even lane's n seed.
        const int rowAi = half ? (H + li) : li;
        const unsigned long long seedA =
            pack2(NEG_LOG2E * (b_ih[rowAi] + b_hh[rowAi]), 0.0f);
        const unsigned long long seedN =
            pack2(half ? 0.0f : b_hh[2 * H + li], 0.0f);
        const float b_in_i = b_ih[2 * H + li];

        // h[li] lives in a register across steps (owned by this lane pair)
        float hold = latent[(size_t)b * H + li];
        pool[half * 132 + li] = hold;          // init parity-0 buffers
        __syncthreads();

        const int widx = half * 132 + li;      // write index within a parity region
        const int roff = half ? 196 : 0;       // n-dot read offset (copy A/B)

        float* rb0 = pool;                     // parity 0 region base
        float* rb1 = pool + PAR_STRIDE;        // parity 1 region base

        float* hs_base = g_hs + (size_t)b * SEQ * H + li;

        // one GRU step: read h from region rbase, write new h to region wbase
        auto step = [&](const float* rbase, float* wbase, int t) {
            // ---- full 128-wide dot of the owned sigmoid gate (broadcast) ----
            const ulonglong2* hA = (const ulonglong2*)rbase;   // copy A
            unsigned long long a0 = seedA, a1 = 0ull;
            #pragma unroll
            for (int k = 0; k < 32; k++) {
                ulonglong2 hv = hA[k];
                a0 = ffma2(wA[2 * k    ], hv.x, a0);
                a1 = ffma2(wA[2 * k + 1], hv.y, a1);
            }
            float sA   = hsum2(add2(a0, a1));
            float sigA = rcpf(1.0f + ex2f(sA));   // r (even) / z (odd); chain
                                                  // hides under the n-dot below
            // ---- pair-split n-dot (same layout as before) ----
            const ulonglong2* hN = (const ulonglong2*)(rbase + roff);
            unsigned long long n0 = seedN, n1 = 0ull;
            #pragma unroll
            for (int k = 0; k < 16; k++) {
                ulonglong2 hv = hN[k];
                n0 = ffma2(wN[2 * k    ], hv.x, n0);
                n1 = ffma2(wN[2 * k + 1], hv.y, n1);
            }
            // exchange the sigmoids (latency overlaps the n reduction)
            float oA  = __shfl_xor_sync(0xffffffffu, sigA, 1);
            float sn  = hsum2(add2(n0, n1));
            float sno = __shfl_xor_sync(0xffffffffu, sn, 1);

            float r  = half ? oA : sigA;
            float z  = half ? sigA : oA;
            float n  = tanh_fast(fmaf(r, sn + sno, b_in_i));
            float hn = fmaf(z, hold - n, n);      // (1-z)*n + z*h
            hold = hn;

            wbase[widx] = hn;                     // both copies get written
            if (half == 0) hs_base[(size_t)t * H] = hn;
            __syncthreads();                      // single barrier per step
        };

        for (int to = 0; to < SEQ; to += 32) {
            #pragma unroll 1
            for (int ti = 0; ti < 32; ti += 2) {
                step(rb0, rb1, to + ti);          // even step: parity 0 -> 1
                step(rb1, rb0, to + ti + 1);      // odd  step: parity 1 -> 0
            }
            if (tid == 0) {
                __threadfence();
                atomicExch(&g_wm[b], to + 32);
            }
        }
    } else {
        // ================= FC role: consume hs tiles as produced =================
        const int fcid = blockIdx.x - NREC;   // 0..83
        const int cb   = fcid / 21;           // fixed 128-col block
        const int sub  = fcid % 21;
        const int col  = cb * H + (tid & 127);
        const int grp  = tid >> 7;            // 2 row-groups over the 32-row tile

        unsigned long long w[64];
        {
            const unsigned long long* Wr =
                (const unsigned long long*)(fc_W + (size_t)col * H);
            #pragma unroll
            for (int k = 0; k < 64; k++) w[k] = Wr[k];
        }
        const float bias = fc_b[col];

        for (int ent = sub; ent < 64 * B; ent += 21) {
            const int tblk = ent >> 6;
            const int bb   = ent & 63;

            if (tid == 0) {
                const int need = (tblk + 1) * 32;
                while (atomicAdd(&g_wm[bb], 0) < need) __nanosleep(256);
            }
            __syncthreads();

            // Stage 32x128 fp32 hs tile (16 KB)
            const float4* src =
                (const float4*)(g_hs + ((size_t)bb * SEQ + (size_t)tblk * 32) * H);
            float4* dst = (float4*)pool;
            #pragma unroll
            for (int it = 0; it < 4; it++) {
                int idx = tid + it * THREADS;
                dst[idx] = src[idx];
            }
            __syncthreads();

            for (int r = grp; r < 32; r += 2) {
                const ulonglong2* hrow = (const ulonglong2*)(pool + r * H);
                unsigned long long a0 = 0ull, a1 = 0ull;
                #pragma unroll
                for (int k = 0; k < 32; k++) {
                    ulonglong2 hv = hrow[k];
                    a0 = ffma2(w[2 * k    ], hv.x, a0);
                    a1 = ffma2(w[2 * k + 1], hv.y, a1);
                }
                out[((size_t)bb * SEQ + (size_t)tblk * 32 + r) * OUTF + col] =
                    hsum2(add2(a0, a1)) + bias;
            }
            __syncthreads();
        }
    }
}

extern "C" void kernel_launch(void* const* d_in, const int* in_sizes, int n_in,
                              void* d_out, int out_size) {
    const float* latent = (const float*)d_in[0];
    const float* W_hh   = (const float*)d_in[1];
    const float* b_ih   = (const float*)d_in[2];
    const float* b_hh   = (const float*)d_in[3];
    const float* fc_W   = (const float*)d_in[4];
    const float* fc_b   = (const float*)d_in[5];
    float* out = (float*)d_out;

    init_wm_kernel<<<1, 64>>>();
    fused_kernel<<<NREC + NFC, THREADS>>>(latent, W_hh, b_ih, b_hh, fc_W, fc_b, out);
}